// round 15
// baseline (speedup 1.0000x reference)
#include <cuda_runtime.h>

#define R_BINS 64
#define Z_BINS 64
#define NBINS  (R_BINS * Z_BINS)
#define HSTRIDE 65                       // pad: bank = (bi + bj) % 32
#define CTAS_PER_SM 5
#define GRID_CTAS (148 * CTAS_PER_SM)    // 5 CTAs/SM co-resident (48 regs <= 51 cap)
#define NTHREADS 256
#define WARPS_PER_CTA (NTHREADS / 32)

#define PI_F     3.14159265358979f
#define INV_DR   6.4f                    // 1/0.15625
#define DR_F     0.15625f
#define DZ_F     0.0625f

__device__ unsigned int g_c1 = 0;        // zeroing-done arrivals (reaches 16)
__device__ unsigned int g_c2 = 0;        // flush-done arrivals (reaches grid)

__device__ __forceinline__ void accum_point(float x, float y, float z, float m,
                                            float* __restrict__ h) {
    float r  = sqrtf(fmaf(x, x, y * y));
    int   bi = (int)(r * INV_DR);                 // r >= 0 -> trunc == floor
    float fj = floorf((z + 2.0f) * 16.0f);
    int   bj = (int)fj;
    if (bi < R_BINS && (unsigned)bj < Z_BINS) {
        atomicAdd(&h[bi * HSTRIDE + bj], m);
    }
}

// Load 4 points (lane-strided by 32) with OOB clamp. 16 independent LDGs.
__device__ __forceinline__ void load_batch(const float* __restrict__ pos,
                                           const float* __restrict__ mass,
                                           int n, int p0,
                                           float* x, float* y, float* z, float* m) {
    #pragma unroll
    for (int k = 0; k < 4; k++) {
        int  p = p0 + 32 * k;
        bool v = p < n;
        int  q = v ? p : (n - 1);
        x[k] = pos[3 * q + 0];
        y[k] = pos[3 * q + 1];
        z[k] = pos[3 * q + 2];
        m[k] = v ? mass[q] : 0.0f;
    }
}

__device__ __forceinline__ void process_batch(const float* x, const float* y,
                                              const float* z, const float* m,
                                              float* __restrict__ hist) {
    #pragma unroll
    for (int k = 0; k < 4; k++)
        accum_point(x[k], y[k], z[k], m[k], hist);
}

__global__ void __launch_bounds__(NTHREADS, CTAS_PER_SM)
fused_hist_kernel(const float* __restrict__ pos,    // (N,3) f32 flat
                  const float* __restrict__ mass,   // (N,)  f32
                  float* __restrict__ out,
                  int n)                            // N
{
    __shared__ float sh[2][R_BINS * HSTRIDE];

    const int tid  = threadIdx.x;
    const int wid  = tid >> 5;
    const int lane = tid & 31;

    // ---- Phase 0: CTAs 0..15 zero d_out (re-zeroed every graph replay)
    if (blockIdx.x < 16) {
        out[blockIdx.x * NTHREADS + tid] = 0.0f;
        __threadfence();
        __syncthreads();
        if (tid == 0) atomicAdd(&g_c1, 1u);
    }

    // ---- Phase 1: private histograms (2 sub-hists by warp parity)
    float* hist = sh[wid & 1];
    for (int i = tid; i < 2 * R_BINS * HSTRIDE; i += NTHREADS)
        (&sh[0][0])[i] = 0.0f;
    __syncthreads();

    // Warp-granular grid stride, 128 points per warp-iter (4/lane, 32-strided).
    // Ping-pong double buffer: next batch's 16 LDGs always in flight while
    // processing the current one; no register-shift MOVs.
    const int gw   = blockIdx.x * WARPS_PER_CTA + wid;
    const int nw   = gridDim.x * WARPS_PER_CTA;
    const int step = nw * 128;

    int base = gw * 128 + lane;
    {
        float xa[4], ya[4], za[4], ma[4];
        float xb[4], yb[4], zb[4], mb[4];

        load_batch(pos, mass, n, base, xa, ya, za, ma);   // batch 0 (A)
        int next = base + step;

        // Steady state: unrolled x2, A/B alternate. Loop while BOTH slots used.
        while (next - lane < n) {
            load_batch(pos, mass, n, next, xb, yb, zb, mb);      // prefetch B
            process_batch(xa, ya, za, ma, hist);                 // process A
            next += step;
            if (next - lane >= n) {                              // B is the last
                process_batch(xb, yb, zb, mb, hist);
                goto done;
            }
            load_batch(pos, mass, n, next, xa, ya, za, ma);      // prefetch A
            process_batch(xb, yb, zb, mb, hist);                 // process B
            next += step;
        }
        process_batch(xa, ya, za, ma, hist);                     // lone A
        done: ;
    }
    __syncthreads();

    // ---- Phase 2: wait until d_out is zeroed (flag set at kernel start by
    // first-wave CTAs 0..15, so no deadlock)
    if (tid == 0) {
        while (atomicAdd(&g_c1, 0u) < 16u) { __nanosleep(64); }
    }
    __syncthreads();
    __threadfence();

    // ---- Phase 3: flush, pre-scaled by 1/volume (normalize folded in)
    for (int i = tid; i < NBINS; i += NTHREADS) {
        int row = i >> 6;
        int col = i & 63;
        float v = sh[0][row * HSTRIDE + col] + sh[1][row * HSTRIDE + col];
        if (v != 0.0f) {
            float r0  = (float)row * DR_F;
            float r1  = (float)(row + 1) * DR_F;
            float vol = PI_F * (r1 * r1 - r0 * r0) * DZ_F;
            atomicAdd(&out[i], v / vol);
        }
    }

    // ---- Phase 4: last CTA resets counters (deterministic across replays)
    __threadfence();
    __syncthreads();
    if (tid == 0) {
        unsigned int v = atomicAdd(&g_c2, 1u);
        if (v == gridDim.x - 1) {
            atomicExch(&g_c1, 0u);
            atomicExch(&g_c2, 0u);
        }
    }
}

extern "C" void kernel_launch(void* const* d_in, const int* in_sizes, int n_in,
                              void* d_out, int out_size) {
    const float* pos  = (const float*)d_in[0];   // positions (N,3) f32
    const float* mass = (const float*)d_in[1];   // masses (N,) f32
    float* out = (float*)d_out;

    int n = in_sizes[1];     // N = 2^24

    fused_hist_kernel<<<GRID_CTAS, NTHREADS>>>(pos, mass, out, n);
}